// round 1
// baseline (speedup 1.0000x reference)
#include <cuda_runtime.h>
#include <math.h>

// ---------------- problem constants ----------------
#define T_TOK   2048
#define H_DIM   2048
#define LATD    1024
#define INTERD  1024
#define NE      32
#define NG      4
#define GSZ     (NE / NG)      // 8 experts per group
#define TOPKG   2
#define TOPK    8
#define SH_INTER 4096
#define NROWS   (T_TOK * TOPK) // 16384 gathered rows
#define RSCALE  2.5f

// ---------------- device scratch (static, no allocs) ----------------
__device__ float g_xlat[T_TOK * LATD];      // 8 MB
__device__ float g_h[NROWS * INTERD];       // 64 MB
__device__ float g_yg[NROWS * LATD];        // 64 MB
__device__ float g_ylat[T_TOK * LATD];      // 8 MB
__device__ float g_routed[T_TOK * H_DIM];   // 16 MB
__device__ float g_s1[T_TOK * SH_INTER];    // 32 MB
__device__ int   g_topi[NROWS];
__device__ float g_wsel[NROWS];
__device__ int   g_counts[NE];
__device__ int   g_off[NE];
__device__ int   g_cursor[NE];
__device__ int   g_gtok[NROWS];
__device__ float g_gw[NROWS];
__device__ int   g_rowidx[NROWS];

// ---------------- gate + routing ----------------
// One block per token. 4 warps compute 32 logits; thread 0 does routing.
__global__ void gate_kernel(const float* __restrict__ x,
                            const float* __restrict__ gw,
                            const float* __restrict__ gb)
{
    int t = blockIdx.x;
    __shared__ float logits[NE];
    int warp = threadIdx.x >> 5, lane = threadIdx.x & 31;
    const float* xt = x + (long)t * H_DIM;
    for (int e = warp; e < NE; e += 4) {
        const float* w = gw + (long)e * H_DIM;
        float s = 0.f;
        for (int h = lane; h < H_DIM; h += 32) s = fmaf(xt[h], w[h], s);
        #pragma unroll
        for (int o = 16; o > 0; o >>= 1) s += __shfl_down_sync(0xffffffffu, s, o);
        if (lane == 0) logits[e] = s;
    }
    __syncthreads();
    if (threadIdx.x == 0) {
        float sc[NE], sb[NE];
        #pragma unroll
        for (int e = 0; e < NE; e++) {
            float s = 1.f / (1.f + expf(-logits[e]));
            sc[e] = s;
            sb[e] = s + gb[e];
        }
        // group scores = sum of top-2 sb within each group of 8
        float gsc[NG];
        #pragma unroll
        for (int g = 0; g < NG; g++) {
            float m1 = -1e30f, m2 = -1e30f;
            #pragma unroll
            for (int j = 0; j < GSZ; j++) {
                float v = sb[g * GSZ + j];
                if (v > m1) { m2 = m1; m1 = v; }
                else if (v > m2) { m2 = v; }
            }
            gsc[g] = m1 + m2;
        }
        // top-2 groups (ties -> lowest index, matching jax top_k)
        int g1 = 0; float b1 = gsc[0];
        for (int g = 1; g < NG; g++) if (gsc[g] > b1) { b1 = gsc[g]; g1 = g; }
        int g2 = -1; float b2 = -1e30f;
        for (int g = 0; g < NG; g++) if (g != g1 && gsc[g] > b2) { b2 = gsc[g]; g2 = g; }
        // top-8 experts among the 2 allowed groups, by sb; weights from raw sc
        bool used[NE];
        #pragma unroll
        for (int e = 0; e < NE; e++) used[e] = !((e / GSZ) == g1 || (e / GSZ) == g2);
        float wtmp[TOPK];
        float wsum = 0.f;
        #pragma unroll
        for (int k = 0; k < TOPK; k++) {
            int best = -1; float bv = -1e30f;
            for (int e = 0; e < NE; e++)
                if (!used[e] && sb[e] > bv) { bv = sb[e]; best = e; }
            used[best] = true;
            g_topi[t * TOPK + k] = best;
            wtmp[k] = sc[best];
            wsum += sc[best];
        }
        float inv = RSCALE / wsum;
        #pragma unroll
        for (int k = 0; k < TOPK; k++) g_wsel[t * TOPK + k] = wtmp[k] * inv;
    }
}

// ---------------- routing buffers ----------------
__global__ void zero_counts_kernel()
{
    if (threadIdx.x < NE) g_counts[threadIdx.x] = 0;
}

__global__ void count_kernel()
{
    int i = blockIdx.x * blockDim.x + threadIdx.x;
    if (i < NROWS) atomicAdd(&g_counts[g_topi[i]], 1);
}

__global__ void scan_kernel()
{
    if (threadIdx.x == 0) {
        int s = 0;
        for (int e = 0; e < NE; e++) {
            g_off[e] = s;
            g_cursor[e] = s;
            s += g_counts[e];
        }
    }
}

__global__ void scatter_kernel()
{
    int i = blockIdx.x * blockDim.x + threadIdx.x;
    if (i < NROWS) {
        int e = g_topi[i];
        int pos = atomicAdd(&g_cursor[e], 1);
        g_gtok[pos] = i / TOPK;
        g_gw[pos]   = g_wsel[i];
        g_rowidx[i] = pos;
    }
}

// ---------------- combine: y_lat[t] = sum_k y_g[rowidx[t,k]] ----------------
__global__ void combine_kernel()
{
    int t = blockIdx.x;
    int l4 = threadIdx.x;           // 256 threads * float4 = 1024 floats
    int ridx[TOPK];
    #pragma unroll
    for (int k = 0; k < TOPK; k++) ridx[k] = g_rowidx[t * TOPK + k];
    float4 s = make_float4(0.f, 0.f, 0.f, 0.f);
    #pragma unroll
    for (int k = 0; k < TOPK; k++) {
        const float4 v = reinterpret_cast<const float4*>(g_yg + (long)ridx[k] * LATD)[l4];
        s.x += v.x; s.y += v.y; s.z += v.z; s.w += v.w;
    }
    reinterpret_cast<float4*>(g_ylat + (long)t * LATD)[l4] = s;
}

// ---------------- generic SGEMM-NT: C[M,N] = A[M,K] * B[N,K]^T ----------------
// 128x128 tile, K-tile 8, 256 threads, 8x8 micro-tile.
// EPI: 0 = store, 1 = relu^2, 2 = relu^2 * row_scale, 3 = store + Cadd
// GATHER: A row index = gidx[row]; GROUPED: per-expert segments (blockIdx.z)
template<int EPI, bool GATHER, bool GROUPED>
__global__ __launch_bounds__(256, 2)
void sgemm_nt(const float* __restrict__ A, const float* __restrict__ Bmat,
              float* __restrict__ C, int M, int N, int K,
              const int* __restrict__ gidx, const float* __restrict__ rscale,
              const float* __restrict__ Cadd,
              const int* __restrict__ goff, const int* __restrict__ gcnt,
              long Bstride)
{
    __shared__ float As[8][128];
    __shared__ float Bs[8][128];

    int row0, rowEnd;
    const float* Bp = Bmat;
    if (GROUPED) {
        int e = blockIdx.z;
        int cnt = gcnt[e];
        if ((int)blockIdx.y * 128 >= cnt) return;
        int off = goff[e];
        row0 = off + blockIdx.y * 128;
        rowEnd = off + cnt;
        Bp += (long)e * Bstride;
    } else {
        row0 = blockIdx.y * 128;
        rowEnd = M;
    }
    const int col0 = blockIdx.x * 128;
    const int tid = threadIdx.x;

    const int lr = tid >> 1;         // 0..127
    const int lk = (tid & 1) * 4;    // 0 or 4

    int arow = -1;
    {
        int r = row0 + lr;
        if (r < rowEnd) arow = GATHER ? gidx[r] : r;
    }
    const int brow = col0 + lr;

    const int trow = (tid >> 4) * 8;
    const int tcol = (tid & 15) * 8;

    float acc[8][8];
    #pragma unroll
    for (int i = 0; i < 8; i++)
        #pragma unroll
        for (int j = 0; j < 8; j++) acc[i][j] = 0.f;

    const float* Aptr = (arow >= 0) ? (A + (long)arow * K + lk) : A;
    const bool avalid = (arow >= 0);
    const float* Bptr = Bp + (long)brow * K + lk;

    for (int k0 = 0; k0 < K; k0 += 8) {
        float4 av = make_float4(0.f, 0.f, 0.f, 0.f);
        if (avalid) av = *reinterpret_cast<const float4*>(Aptr + k0);
        float4 bv = *reinterpret_cast<const float4*>(Bptr + k0);
        As[lk + 0][lr] = av.x; As[lk + 1][lr] = av.y;
        As[lk + 2][lr] = av.z; As[lk + 3][lr] = av.w;
        Bs[lk + 0][lr] = bv.x; Bs[lk + 1][lr] = bv.y;
        Bs[lk + 2][lr] = bv.z; Bs[lk + 3][lr] = bv.w;
        __syncthreads();
        #pragma unroll
        for (int kk = 0; kk < 8; kk++) {
            float a[8], b[8];
            #pragma unroll
            for (int i = 0; i < 8; i++) a[i] = As[kk][trow + i];
            #pragma unroll
            for (int j = 0; j < 8; j++) b[j] = Bs[kk][tcol + j];
            #pragma unroll
            for (int i = 0; i < 8; i++)
                #pragma unroll
                for (int j = 0; j < 8; j++)
                    acc[i][j] = fmaf(a[i], b[j], acc[i][j]);
        }
        __syncthreads();
    }

    #pragma unroll
    for (int i = 0; i < 8; i++) {
        int r = row0 + trow + i;
        if (r >= rowEnd) continue;
        float w = (EPI == 2) ? rscale[r] : 0.f;
        float* crow = C + (long)r * N + col0 + tcol;
        const float* addrow = (EPI == 3) ? (Cadd + (long)r * N + col0 + tcol) : nullptr;
        #pragma unroll
        for (int j = 0; j < 8; j++) {
            float v = acc[i][j];
            if (EPI == 1) { float u = fmaxf(v, 0.f); v = u * u; }
            if (EPI == 2) { float u = fmaxf(v, 0.f); v = u * u * w; }
            if (EPI == 3) { v += addrow[j]; }
            crow[j] = v;
        }
    }
}

// ---------------- launch ----------------
extern "C" void kernel_launch(void* const* d_in, const int* in_sizes, int n_in,
                              void* d_out, int out_size)
{
    const float* x        = (const float*)d_in[0]; // [T, H]
    const float* gate_w   = (const float*)d_in[1]; // [E, H]
    const float* gate_b   = (const float*)d_in[2]; // [E]
    const float* fc1_w    = (const float*)d_in[3]; // [LAT, H]
    const float* fc2_w    = (const float*)d_in[4]; // [H, LAT]
    const float* w1       = (const float*)d_in[5]; // [E, INTER, LAT]
    const float* w2       = (const float*)d_in[6]; // [E, LAT, INTER]
    const float* sup      = (const float*)d_in[7]; // [SH_INTER, H]
    const float* sdn      = (const float*)d_in[8]; // [H, SH_INTER]
    float* out = (float*)d_out;

    void *p_xlat, *p_h, *p_yg, *p_ylat, *p_routed, *p_s1;
    void *p_gtok, *p_gw, *p_off, *p_cnt;
    cudaGetSymbolAddress(&p_xlat,   g_xlat);
    cudaGetSymbolAddress(&p_h,      g_h);
    cudaGetSymbolAddress(&p_yg,     g_yg);
    cudaGetSymbolAddress(&p_ylat,   g_ylat);
    cudaGetSymbolAddress(&p_routed, g_routed);
    cudaGetSymbolAddress(&p_s1,     g_s1);
    cudaGetSymbolAddress(&p_gtok,   g_gtok);
    cudaGetSymbolAddress(&p_gw,     g_gw);
    cudaGetSymbolAddress(&p_off,    g_off);
    cudaGetSymbolAddress(&p_cnt,    g_counts);

    // 1) gate + routing decisions
    gate_kernel<<<T_TOK, 128>>>(x, gate_w, gate_b);

    // 2) build expert segments
    zero_counts_kernel<<<1, 32>>>();
    count_kernel<<<(NROWS + 255) / 256, 256>>>();
    scan_kernel<<<1, 32>>>();
    scatter_kernel<<<(NROWS + 255) / 256, 256>>>();

    // 3) x_lat = x @ fc1^T   [2048x1024], K=2048
    sgemm_nt<0, false, false><<<dim3(LATD / 128, T_TOK / 128), 256>>>(
        x, fc1_w, (float*)p_xlat, T_TOK, LATD, H_DIM,
        nullptr, nullptr, nullptr, nullptr, nullptr, 0);

    // 4) grouped GEMM 1: h = relu2(x_lat[gather] @ w1[e]^T) * gw   K=LAT
    sgemm_nt<2, true, true><<<dim3(INTERD / 128, T_TOK / 128, NE), 256>>>(
        (const float*)p_xlat, w1, (float*)p_h, 0, INTERD, LATD,
        (const int*)p_gtok, (const float*)p_gw, nullptr,
        (const int*)p_off, (const int*)p_cnt, (long)INTERD * LATD);

    // 5) grouped GEMM 2: y_g = h @ w2[e]^T   K=INTER
    sgemm_nt<0, false, true><<<dim3(LATD / 128, T_TOK / 128, NE), 256>>>(
        (const float*)p_h, w2, (float*)p_yg, 0, LATD, INTERD,
        nullptr, nullptr, nullptr,
        (const int*)p_off, (const int*)p_cnt, (long)LATD * INTERD);

    // 6) combine per-token expert outputs
    combine_kernel<<<T_TOK, 256>>>();

    // 7) routed = y_lat @ fc2^T   [2048x2048], K=1024
    sgemm_nt<0, false, false><<<dim3(H_DIM / 128, T_TOK / 128), 256>>>(
        (const float*)p_ylat, fc2_w, (float*)p_routed, T_TOK, H_DIM, LATD,
        nullptr, nullptr, nullptr, nullptr, nullptr, 0);

    // 8) shared up: s1 = relu2(x @ sup^T)   [2048x4096], K=2048
    sgemm_nt<1, false, false><<<dim3(SH_INTER / 128, T_TOK / 128), 256>>>(
        x, sup, (float*)p_s1, T_TOK, SH_INTER, H_DIM,
        nullptr, nullptr, nullptr, nullptr, nullptr, 0);

    // 9) out = s1 @ sdn^T + routed   [2048x2048], K=4096
    sgemm_nt<3, false, false><<<dim3(H_DIM / 128, T_TOK / 128), 256>>>(
        (const float*)p_s1, sdn, out, T_TOK, H_DIM, SH_INTER,
        nullptr, nullptr, (const float*)p_routed,
        nullptr, nullptr, 0);
}